// round 3
// baseline (speedup 1.0000x reference)
#include <cuda_runtime.h>
#include <cuda_fp16.h>
#include <cstdint>
#include <cstddef>

// Problem dims
#define BB 64
#define NI 1024
#define DI 16
#define NJ 32
#define DJ 32
#define IPW 32              // i's handled per warp in routing passes
#define PASS_BLOCKS_Y (NI / (8 * IPW))   // 8 warps per block

// Scratch (device globals; no dynamic allocation allowed)
__device__ __align__(16) __half g_hat[(size_t)BB * NI * NJ * DJ];  // 128 MB
__device__ __align__(16) float  g_b1[(size_t)BB * NI * NJ];        // logits after iter 1 (8 MB)
__device__ __align__(16) float  g_acc[BB * NJ * DJ];               // pre-squash accumulator
__device__ __align__(16) float  g_outprev[BB * NJ * DJ];           // squashed outputs of prev iter

// ---------- packed f32x2 helpers ----------
__device__ __forceinline__ unsigned long long pack2f(float x, float y) {
    unsigned long long r;
    asm("mov.b64 %0, {%1, %2};" : "=l"(r) : "f"(x), "f"(y));
    return r;
}
__device__ __forceinline__ unsigned long long ffma2(unsigned long long a, unsigned long long b,
                                                    unsigned long long c) {
    unsigned long long d;
    asm("fma.rn.f32x2 %0, %1, %2, %3;" : "=l"(d) : "l"(a), "l"(b), "l"(c));
    return d;
}
__device__ __forceinline__ float2 unpack2f(unsigned long long v) {
    float lo, hi;
    asm("mov.b64 {%0, %1}, %2;" : "=f"(lo), "=f"(hi) : "l"(v));
    return make_float2(lo, hi);
}

// ============================================================================
// K1: hat[b,i,j,m] = sum_n W[i,j,n,m] * x[b,i,n], stored fp16.
// grid = NI blocks (one i each), 256 threads. Thread t owns jm = 4t..4t+3.
// Blocks 0..255 also zero g_acc so pass<0> starts clean (no extra kernel).
// ============================================================================
__global__ __launch_bounds__(256) void k_hat(const float* __restrict__ inp,
                                             const float* __restrict__ W) {
    const int i = blockIdx.x;
    const int t = threadIdx.x;

    if (i < 256) g_acc[i * 256 + t] = 0.f;   // 256*256 = 65536 = BB*NJ*DJ

    const int j  = t >> 3;
    const int m0 = (4 * t) & 31;

    const float4* Wp = reinterpret_cast<const float4*>(
        W + ((size_t)i * NJ + j) * (DI * DJ) + m0);
    unsigned long long w01[16], w23[16];
#pragma unroll
    for (int n = 0; n < 16; n++) {
        float4 w = Wp[n * (DJ / 4)];
        w01[n] = pack2f(w.x, w.y);
        w23[n] = pack2f(w.z, w.w);
    }

    __shared__ float s_in[2][DI];

    for (int b = 0; b < BB; b++) {
        const int buf = b & 1;
        if (t < DI) s_in[buf][t] = inp[((size_t)b * NI + i) * DI + t];
        __syncthreads();

        unsigned long long a01 = 0ULL, a23 = 0ULL;
#pragma unroll
        for (int n = 0; n < 16; n++) {
            float x = s_in[buf][n];
            unsigned long long xx = pack2f(x, x);
            a01 = ffma2(xx, w01[n], a01);
            a23 = ffma2(xx, w23[n], a23);
        }
        float2 f01 = unpack2f(a01);
        float2 f23 = unpack2f(a23);
        __half2 h0 = __floats2half2_rn(f01.x, f01.y);
        __half2 h1 = __floats2half2_rn(f23.x, f23.y);
        uint2 st;
        st.x = reinterpret_cast<uint32_t&>(h0);
        st.y = reinterpret_cast<uint32_t&>(h1);
        *reinterpret_cast<uint2*>(&g_hat[((size_t)b * NI + i) * (NJ * DJ) + 4 * t]) = st;
    }
}

// ============================================================================
// Routing pass. warp = one (b, i-chunk); lane = output capsule j.
// out_prev lives in smem TRANSPOSED (s_opT[m][j] -> lane j reads bank j,
// conflict-free) so the per-thread register count stays < 128 at occ 2.
// ============================================================================
template <int ITER>
__global__ __launch_bounds__(256, 2) void k_pass() {
    const int b    = blockIdx.x;
    const int warp = threadIdx.x >> 5;
    const int j    = threadIdx.x & 31;
    const int wg   = blockIdx.y * 8 + warp;
    const int i0   = wg * IPW;

    __shared__ float s_opT[DJ][NJ];   // [m][j]
    if (ITER > 0) {
        // 1024 floats loaded coalesced (float4), written transposed.
        const int t = threadIdx.x;
        const float4* o4 = reinterpret_cast<const float4*>(&g_outprev[b * NJ * DJ]);
        float4 f = o4[t];
        const int jj = t >> 3;          // (4t)/32
        const int mm = (4 * t) & 31;
        s_opT[mm + 0][jj] = f.x;
        s_opT[mm + 1][jj] = f.y;
        s_opT[mm + 2][jj] = f.z;
        s_opT[mm + 3][jj] = f.w;
        __syncthreads();
    }

    float acc[32];
#pragma unroll
    for (int m = 0; m < 32; m++) acc[m] = 0.f;

    const uint4* p = reinterpret_cast<const uint4*>(
        &g_hat[((size_t)b * NI + i0) * (NJ * DJ) + j * DJ]);
    uint4 q0 = p[0], q1 = p[1], q2 = p[2], q3 = p[3];

    for (int it = 0; it < IPW; it++) {
        const int nx = (it + 1 < IPW) ? (it + 1) : it;
        const uint4* pn = p + (size_t)nx * 128;   // 128 uint4 = 2048 B = one i
        uint4 n0 = pn[0], n1 = pn[1], n2 = pn[2], n3 = pn[3];

        uint32_t qw[16] = {q0.x, q0.y, q0.z, q0.w, q1.x, q1.y, q1.z, q1.w,
                           q2.x, q2.y, q2.z, q2.w, q3.x, q3.y, q3.z, q3.w};
        float h[32];
#pragma unroll
        for (int k = 0; k < 16; k++) {
            __half2 hh = reinterpret_cast<__half2&>(qw[k]);
            float2 f = __half22float2(hh);
            h[2 * k] = f.x; h[2 * k + 1] = f.y;
        }

        float c;
        if (ITER == 0) {
            c = 1.0f / 32.0f;
        } else {
            float logit = 0.f;
#pragma unroll
            for (int m = 0; m < 32; m++) logit = fmaf(s_opT[m][j], h[m], logit);
            const int i = i0 + it;
            if (ITER == 2) logit += g_b1[((size_t)b * NI + i) * NJ + j];
            if (ITER == 1) g_b1[((size_t)b * NI + i) * NJ + j] = logit;

            float mx = logit;
#pragma unroll
            for (int o = 16; o > 0; o >>= 1)
                mx = fmaxf(mx, __shfl_xor_sync(0xffffffffu, mx, o));
            float e = __expf(logit - mx);
            float s = e;
#pragma unroll
            for (int o = 16; o > 0; o >>= 1)
                s += __shfl_xor_sync(0xffffffffu, s, o);
            c = e / s;
        }

#pragma unroll
        for (int m = 0; m < 32; m++) acc[m] = fmaf(c, h[m], acc[m]);

        q0 = n0; q1 = n1; q2 = n2; q3 = n3;
    }

    float* ap = &g_acc[(b * NJ + j) * DJ];
#pragma unroll
    for (int m = 0; m < 32; m++) atomicAdd(ap + m, acc[m]);
}

// ============================================================================
// Squash + re-zero g_acc for the next pass (fused; replaces k_zero_acc).
// grid = BB blocks, 1024 threads; warp = j, lane = m.
// ============================================================================
template <int LAST>
__global__ void k_squash(float* __restrict__ out) {
    const int b = blockIdx.x;
    const int j = threadIdx.x >> 5;
    const int m = threadIdx.x & 31;
    const int idx = (b * NJ + j) * DJ + m;
    float s = g_acc[idx];
    g_acc[idx] = 0.f;
    float sq = s * s;
#pragma unroll
    for (int o = 16; o > 0; o >>= 1)
        sq += __shfl_xor_sync(0xffffffffu, sq, o);
    float scale = sq / ((1.f + sq) * sqrtf(sq + 1e-7f));
    float r = scale * s;
    if (LAST) out[idx] = r;
    else      g_outprev[idx] = r;
}

// ============================================================================
extern "C" void kernel_launch(void* const* d_in, const int* in_sizes, int n_in,
                              void* d_out, int out_size) {
    const float* inp = (const float*)d_in[0];  // [64, 1024, 16]
    const float* W   = (const float*)d_in[1];  // [1024, 32, 16, 32]
    float* out = (float*)d_out;                // [64, 32, 32]

    const dim3 passGrid(BB, PASS_BLOCKS_Y);

    k_hat<<<NI, 256>>>(inp, W);

    k_pass<0><<<passGrid, 256>>>();
    k_squash<0><<<BB, 1024>>>(nullptr);

    k_pass<1><<<passGrid, 256>>>();
    k_squash<0><<<BB, 1024>>>(nullptr);

    k_pass<2><<<passGrid, 256>>>();
    k_squash<1><<<BB, 1024>>>(out);
}